// round 3
// baseline (speedup 1.0000x reference)
#include <cuda_runtime.h>
#include <math_constants.h>

// Problem constants (fixed shapes for Upsample_25056839205742)
#define CIN   384
#define COUT  192
#define NB    4
#define NPER  4096          // coarse points per batch
#define MPER  16384         // fine points per batch
#define NTOT  (NB * NPER)   // 16384
#define MTOT  (NB * MPER)   // 65536
#define LN_EPS 1e-5f

// Scratch (static device arrays — no allocation allowed)
__device__ float g_h [(size_t)NTOT * COUT];   // branch-2 LN+Linear output
__device__ float g_wk[(size_t)MTOT * 3];      // interp weights
__device__ int   g_ik[(size_t)MTOT * 3];      // interp source rows (global coarse index)

__device__ __forceinline__ float warp_sum(float v) {
#pragma unroll
    for (int o = 16; o > 0; o >>= 1) v += __shfl_xor_sync(0xffffffffu, v, o);
    return v;
}

// ---------------------------------------------------------------------------
// Kernel 1: h = LN(feats; ln2) @ w2 + b2       [NTOT x CIN] -> [NTOT x COUT]
// block = 192 threads, 16 rows per block
// ---------------------------------------------------------------------------
__global__ __launch_bounds__(192) void k_ln_gemm2(
    const float* __restrict__ feats,
    const float* __restrict__ ln_g, const float* __restrict__ ln_b,
    const float* __restrict__ w,    const float* __restrict__ bias)
{
    __shared__ __align__(16) float xn[16][CIN];
    const int tid = threadIdx.x, wid = tid >> 5, lane = tid & 31;
    const int row0 = blockIdx.x * 16;

    // ----- LayerNorm phase: warp w handles rows w, w+6, ...
    for (int r = wid; r < 16; r += 6) {
        const float* x = feats + (size_t)(row0 + r) * CIN;
        float v[12];
        float s = 0.f, ss = 0.f;
#pragma unroll
        for (int t = 0; t < 12; t++) {
            v[t] = x[lane + 32 * t];
            s  += v[t];
            ss += v[t] * v[t];
        }
        s  = warp_sum(s);
        ss = warp_sum(ss);
        const float mu  = s * (1.0f / CIN);
        const float inv = rsqrtf(ss * (1.0f / CIN) - mu * mu + LN_EPS);
#pragma unroll
        for (int t = 0; t < 12; t++) {
            const int k = lane + 32 * t;
            xn[r][k] = (v[t] - mu) * inv * ln_g[k] + ln_b[k];
        }
    }
    __syncthreads();

    // ----- GEMM phase: thread j owns output column j for all 16 rows
    const int j = tid;
    float acc[16];
#pragma unroll
    for (int r = 0; r < 16; r++) acc[r] = 0.f;

    for (int k = 0; k < CIN; k += 4) {
        const float w0 = w[(size_t)(k + 0) * COUT + j];
        const float w1 = w[(size_t)(k + 1) * COUT + j];
        const float w2 = w[(size_t)(k + 2) * COUT + j];
        const float w3 = w[(size_t)(k + 3) * COUT + j];
#pragma unroll
        for (int r = 0; r < 16; r++) {
            const float4 x4 = *reinterpret_cast<const float4*>(&xn[r][k]);
            acc[r] = fmaf(x4.x, w0, acc[r]);
            acc[r] = fmaf(x4.y, w1, acc[r]);
            acc[r] = fmaf(x4.z, w2, acc[r]);
            acc[r] = fmaf(x4.w, w3, acc[r]);
        }
    }
    const float bb = bias[j];
#pragma unroll
    for (int r = 0; r < 16; r++)
        g_h[(size_t)(row0 + r) * COUT + j] = acc[r] + bb;
}

// ---------------------------------------------------------------------------
// Kernel 2: brute-force 3-NN per fine point, inverse-distance weights
// block = 256 threads, 1 query/thread, candidates staged in smem (2 chunks)
// d^2 computed DIRECTLY from coordinate differences (no |c|^2 trick) to match
// the reference numerics without catastrophic cancellation.
// ---------------------------------------------------------------------------
__global__ __launch_bounds__(256) void k_knn(
    const float* __restrict__ xyz,       // coarse [NTOT,3]
    const float* __restrict__ sxyz)      // fine   [MTOT,3]
{
    __shared__ __align__(16) float4 cand[2048];
    const int q = blockIdx.x * 256 + threadIdx.x;   // global fine index
    const int b = q / MPER;                          // uniform per block (256 | MPER)

    const float qx = sxyz[q * 3 + 0];
    const float qy = sxyz[q * 3 + 1];
    const float qz = sxyz[q * 3 + 2];

    float s0 = CUDART_INF_F, s1 = CUDART_INF_F, s2 = CUDART_INF_F;
    int   i0 = 0, i1 = 0, i2 = 0;

    for (int chunk = 0; chunk < NPER / 2048; chunk++) {
        const int base = b * NPER + chunk * 2048;
        __syncthreads();
        for (int i = threadIdx.x; i < 2048; i += 256) {
            const float cx = xyz[(size_t)(base + i) * 3 + 0];
            const float cy = xyz[(size_t)(base + i) * 3 + 1];
            const float cz = xyz[(size_t)(base + i) * 3 + 2];
            cand[i] = make_float4(cx, cy, cz, 0.f);
        }
        __syncthreads();

#pragma unroll 4
        for (int i = 0; i < 2048; i++) {
            const float4 c = cand[i];
            const float dx = qx - c.x;
            const float dy = qy - c.y;
            const float dz = qz - c.z;
            const float s = fmaf(dx, dx, fmaf(dy, dy, dz * dz));  // exact d^2
            if (s < s2) {
                const int gi = base + i;
                if (s < s1) {
                    s2 = s1; i2 = i1;
                    if (s < s0) { s1 = s0; i1 = i0; s0 = s; i0 = gi; }
                    else        { s1 = s;  i1 = gi; }
                } else {
                    s2 = s; i2 = gi;
                }
            }
        }
    }

    const float d0 = sqrtf(fmaxf(s0, 0.f));
    const float d1 = sqrtf(fmaxf(s1, 0.f));
    const float d2 = sqrtf(fmaxf(s2, 0.f));
    const float r0 = 1.0f / (d0 + 1e-8f);
    const float r1 = 1.0f / (d1 + 1e-8f);
    const float r2 = 1.0f / (d2 + 1e-8f);
    const float rs = 1.0f / (r0 + r1 + r2);

    g_wk[q * 3 + 0] = r0 * rs;  g_ik[q * 3 + 0] = i0;
    g_wk[q * 3 + 1] = r1 * rs;  g_ik[q * 3 + 1] = i1;
    g_wk[q * 3 + 2] = r2 * rs;  g_ik[q * 3 + 2] = i2;
}

// ---------------------------------------------------------------------------
// Kernel 3: out = LN(support_feats; ln1) @ w1 + b1 + interp-gather(g_h)
// block = 192 threads, 16 rows per block
// ---------------------------------------------------------------------------
__global__ __launch_bounds__(192) void k_ln_gemm1(
    const float* __restrict__ sfeats,
    const float* __restrict__ ln_g, const float* __restrict__ ln_b,
    const float* __restrict__ w,    const float* __restrict__ bias,
    float* __restrict__ out)
{
    __shared__ __align__(16) float xn[16][COUT];
    const int tid = threadIdx.x, wid = tid >> 5, lane = tid & 31;
    const int row0 = blockIdx.x * 16;

    for (int r = wid; r < 16; r += 6) {
        const float* x = sfeats + (size_t)(row0 + r) * COUT;
        float v[6];
        float s = 0.f, ss = 0.f;
#pragma unroll
        for (int t = 0; t < 6; t++) {
            v[t] = x[lane + 32 * t];
            s  += v[t];
            ss += v[t] * v[t];
        }
        s  = warp_sum(s);
        ss = warp_sum(ss);
        const float mu  = s * (1.0f / COUT);
        const float inv = rsqrtf(ss * (1.0f / COUT) - mu * mu + LN_EPS);
#pragma unroll
        for (int t = 0; t < 6; t++) {
            const int k = lane + 32 * t;
            xn[r][k] = (v[t] - mu) * inv * ln_g[k] + ln_b[k];
        }
    }
    __syncthreads();

    const int j = tid;
    float acc[16];
#pragma unroll
    for (int r = 0; r < 16; r++) acc[r] = 0.f;

    for (int k = 0; k < COUT; k += 4) {
        const float w0 = w[(size_t)(k + 0) * COUT + j];
        const float w1 = w[(size_t)(k + 1) * COUT + j];
        const float w2 = w[(size_t)(k + 2) * COUT + j];
        const float w3 = w[(size_t)(k + 3) * COUT + j];
#pragma unroll
        for (int r = 0; r < 16; r++) {
            const float4 x4 = *reinterpret_cast<const float4*>(&xn[r][k]);
            acc[r] = fmaf(x4.x, w0, acc[r]);
            acc[r] = fmaf(x4.y, w1, acc[r]);
            acc[r] = fmaf(x4.z, w2, acc[r]);
            acc[r] = fmaf(x4.w, w3, acc[r]);
        }
    }

    const float bb = bias[j];
#pragma unroll
    for (int r = 0; r < 16; r++) {
        const int row = row0 + r;
        const float wa = g_wk[row * 3 + 0];
        const float wb = g_wk[row * 3 + 1];
        const float wc = g_wk[row * 3 + 2];
        const int   ia = g_ik[row * 3 + 0];
        const int   ib = g_ik[row * 3 + 1];
        const int   ic = g_ik[row * 3 + 2];
        float v = acc[r] + bb;
        v = fmaf(wa, g_h[(size_t)ia * COUT + j], v);
        v = fmaf(wb, g_h[(size_t)ib * COUT + j], v);
        v = fmaf(wc, g_h[(size_t)ic * COUT + j], v);
        out[(size_t)row * COUT + j] = v;
    }
}

// ---------------------------------------------------------------------------
// Kernel 4: output tail — support_xyz pass-through + offsets (value-cast)
// ---------------------------------------------------------------------------
__global__ void k_tail(const float* __restrict__ sxyz,
                       const int* __restrict__ soff,
                       float* __restrict__ out, int extra)
{
    const int i = blockIdx.x * blockDim.x + threadIdx.x;
    if (i >= extra) return;
    const size_t base = (size_t)MTOT * COUT;
    if (i < MTOT * 3) {
        out[base + i] = sxyz[i];
    } else if (i - MTOT * 3 < NB) {
        out[base + i] = (float)soff[i - MTOT * 3];
    }
}

// ---------------------------------------------------------------------------
extern "C" void kernel_launch(void* const* d_in, const int* in_sizes, int n_in,
                              void* d_out, int out_size)
{
    // metadata order: feats, xyz, support_xyz, support_feats, offset,
    //                 support_offset, ln1_g, ln1_b, w1, b1, ln2_g, ln2_b, w2, b2
    const float* feats  = (const float*)d_in[0];
    const float* xyz    = (const float*)d_in[1];
    const float* sxyz   = (const float*)d_in[2];
    const float* sfeats = (const float*)d_in[3];
    const int*   soff   = (const int*)  d_in[5];
    const float* ln1_g  = (const float*)d_in[6];
    const float* ln1_b  = (const float*)d_in[7];
    const float* w1     = (const float*)d_in[8];
    const float* b1     = (const float*)d_in[9];
    const float* ln2_g  = (const float*)d_in[10];
    const float* ln2_b  = (const float*)d_in[11];
    const float* w2     = (const float*)d_in[12];
    const float* b2     = (const float*)d_in[13];
    float* out = (float*)d_out;

    // branch 2: LN + Linear on coarse feats
    k_ln_gemm2<<<NTOT / 16, 192>>>(feats, ln2_g, ln2_b, w2, b2);
    // 3-NN + inverse-distance weights (independent of k1)
    k_knn<<<MTOT / 256, 256>>>(xyz, sxyz);
    // branch 1: LN + Linear + fused interp gather + add
    k_ln_gemm1<<<MTOT / 16, 192>>>(sfeats, ln1_g, ln1_b, w1, b1, out);

    // output tail (support_xyz, support_offset) if the harness buffer holds the tuple
    const long long main_sz = (long long)MTOT * COUT;
    if ((long long)out_size > main_sz) {
        int extra = (int)((long long)out_size - main_sz);
        k_tail<<<(extra + 255) / 256, 256>>>(sxyz, soff, out, extra);
    }
}

// round 4
// speedup vs baseline: 1.2859x; 1.2859x over previous
#include <cuda_runtime.h>
#include <math_constants.h>

#define CIN   384
#define COUT  192
#define NB    4
#define NPER  4096
#define MPER  16384
#define NTOT  (NB * NPER)   // 16384
#define MTOT  (NB * MPER)   // 65536
#define LN_EPS 1e-5f

#define GRID_R 8
#define NCELL  (GRID_R * GRID_R * GRID_R)   // 512
#define TCELL  (NB * NCELL)                 // 2048
#define CELL_H (1.0f / GRID_R)

typedef unsigned long long ull;

// ------------------------- static device scratch ---------------------------
__device__ float  g_h [(size_t)NTOT * COUT];
__device__ float  g_wk[(size_t)MTOT * 3];
__device__ int    g_ik[(size_t)MTOT * 3];
__device__ int    g_cnt[TCELL];
__device__ int    g_cellstart[TCELL + 1];
__device__ int    g_fill[TCELL];
__device__ float4 g_pts4[NTOT];

// ------------------------- helpers -----------------------------------------
__device__ __forceinline__ float warp_sum(float v) {
#pragma unroll
    for (int o = 16; o > 0; o >>= 1) v += __shfl_xor_sync(0xffffffffu, v, o);
    return v;
}

__device__ __forceinline__ ull pack2(float lo, float hi) {
    ull r;
    asm("mov.b64 %0, {%1, %2};" : "=l"(r) : "f"(lo), "f"(hi));
    return r;
}
__device__ __forceinline__ void unpack2(ull v, float& lo, float& hi) {
    asm("mov.b64 {%0, %1}, %2;" : "=f"(lo), "=f"(hi) : "l"(v));
}
// packed 2-wide fp32 FMA (Blackwell FFMA2; only reachable via PTX)
__device__ __forceinline__ ull ffma2(ull a, ull b, ull c) {
    ull d;
    asm("fma.rn.f32x2 %0, %1, %2, %3;" : "=l"(d) : "l"(a), "l"(b), "l"(c));
    return d;
}

__device__ __forceinline__ int cell1(float v) {
    int c = (int)(v * GRID_R);
    return min(GRID_R - 1, max(0, c));
}

// ------------------------- grid build --------------------------------------
__global__ void k_grid_zero() {
    int i = blockIdx.x * 1024 + threadIdx.x;
    if (i < TCELL) g_cnt[i] = 0;
}

__global__ __launch_bounds__(256) void k_grid_count(const float* __restrict__ xyz) {
    int i = blockIdx.x * 256 + threadIdx.x;   // i < NTOT
    int b = i >> 12;                           // NPER = 4096
    int cx = cell1(xyz[i * 3 + 0]);
    int cy = cell1(xyz[i * 3 + 1]);
    int cz = cell1(xyz[i * 3 + 2]);
    atomicAdd(&g_cnt[b * NCELL + (cz * GRID_R + cy) * GRID_R + cx], 1);
}

__global__ __launch_bounds__(1024) void k_grid_scan() {
    __shared__ int A[TCELL], B[TCELL];
    int t = threadIdx.x;
    A[t]        = g_cnt[t];
    A[t + 1024] = g_cnt[t + 1024];
    __syncthreads();
    int* src = A; int* dst = B;
    for (int off = 1; off < TCELL; off <<= 1) {
        dst[t]        = src[t]        + (t        >= off ? src[t        - off] : 0);
        dst[t + 1024] = src[t + 1024] + (t + 1024 >= off ? src[t + 1024 - off] : 0);
        __syncthreads();
        int* tmp = src; src = dst; dst = tmp;
    }
    int ex0 = (t == 0) ? 0 : src[t - 1];
    g_cellstart[t] = ex0;        g_fill[t] = ex0;
    int u = t + 1024;
    int ex1 = src[u - 1];
    g_cellstart[u] = ex1;        g_fill[u] = ex1;
    if (t == 0) g_cellstart[TCELL] = NTOT;
}

__global__ __launch_bounds__(256) void k_grid_scatter(const float* __restrict__ xyz) {
    int i = blockIdx.x * 256 + threadIdx.x;
    int b = i >> 12;
    float x = xyz[i * 3 + 0], y = xyz[i * 3 + 1], z = xyz[i * 3 + 2];
    int cid = b * NCELL + (cell1(z) * GRID_R + cell1(y)) * GRID_R + cell1(x);
    int pos = atomicAdd(&g_fill[cid], 1);
    g_pts4[pos] = make_float4(x, y, z, __int_as_float(i));
}

// ------------------------- grid 3-NN ---------------------------------------
__global__ __launch_bounds__(256) void k_knn_grid(const float* __restrict__ sxyz) {
    const int q = blockIdx.x * 256 + threadIdx.x;   // q < MTOT
    const int b = q >> 14;                           // MPER = 16384
    const float qx = sxyz[q * 3 + 0];
    const float qy = sxyz[q * 3 + 1];
    const float qz = sxyz[q * 3 + 2];
    const int cx = cell1(qx), cy = cell1(qy), cz = cell1(qz);
    const int base = b * NCELL;

    float s0 = CUDART_INF_F, s1 = CUDART_INF_F, s2 = CUDART_INF_F;
    int   i0 = 0, i1 = 0, i2 = 0;

    bool done = false;
    for (int R = 0; R < GRID_R && !done; R++) {
        const int zl = max(0, cz - R), zh = min(GRID_R - 1, cz + R);
        const int yl = max(0, cy - R), yh = min(GRID_R - 1, cy + R);
        const int xl = max(0, cx - R), xh = min(GRID_R - 1, cx + R);
        for (int Z = zl; Z <= zh; Z++) {
            const bool zedge = (Z == cz - R) || (Z == cz + R);
            for (int Y = yl; Y <= yh; Y++) {
                const bool yedge = (Y == cy - R) || (Y == cy + R);
                const int rowb = base + (Z * GRID_R + Y) * GRID_R;
                int lo, hi;
                if (R == 0 || zedge || yedge) {           // full row of new cells
                    lo = g_cellstart[rowb + xl];
                    hi = g_cellstart[rowb + xh + 1];
                    for (int j = lo; j < hi; j++) {
                        const float4 p = g_pts4[j];
                        const float dx = qx - p.x, dy = qy - p.y, dz = qz - p.z;
                        const float s = fmaf(dx, dx, fmaf(dy, dy, dz * dz));
                        if (s < s2) {
                            const int gi = __float_as_int(p.w);
                            if (s < s1) { s2 = s1; i2 = i1;
                                if (s < s0) { s1 = s0; i1 = i0; s0 = s; i0 = gi; }
                                else        { s1 = s;  i1 = gi; } }
                            else { s2 = s; i2 = gi; }
                        }
                    }
                } else {                                   // only the two X-edge cells
#pragma unroll
                    for (int e = 0; e < 2; e++) {
                        const int X = (e == 0) ? (cx - R) : (cx + R);
                        if (X < 0 || X >= GRID_R) continue;
                        lo = g_cellstart[rowb + X];
                        hi = g_cellstart[rowb + X + 1];
                        for (int j = lo; j < hi; j++) {
                            const float4 p = g_pts4[j];
                            const float dx = qx - p.x, dy = qy - p.y, dz = qz - p.z;
                            const float s = fmaf(dx, dx, fmaf(dy, dy, dz * dz));
                            if (s < s2) {
                                const int gi = __float_as_int(p.w);
                                if (s < s1) { s2 = s1; i2 = i1;
                                    if (s < s0) { s1 = s0; i1 = i0; s0 = s; i0 = gi; }
                                    else        { s1 = s;  i1 = gi; } }
                                else { s2 = s; i2 = gi; }
                            }
                        }
                    }
                }
            }
        }
        // coverage bound: ball of radius rc around q is fully inside processed box
        float rc = CUDART_INF_F;
        if (cx - R > 0)          rc = fminf(rc, qx - (cx - R) * CELL_H);
        if (cx + R < GRID_R - 1) rc = fminf(rc, (cx + R + 1) * CELL_H - qx);
        if (cy - R > 0)          rc = fminf(rc, qy - (cy - R) * CELL_H);
        if (cy + R < GRID_R - 1) rc = fminf(rc, (cy + R + 1) * CELL_H - qy);
        if (cz - R > 0)          rc = fminf(rc, qz - (cz - R) * CELL_H);
        if (cz + R < GRID_R - 1) rc = fminf(rc, (cz + R + 1) * CELL_H - qz);
        if (s2 < rc * rc) done = true;   // rc==INF (all covered) also terminates
    }

    const float d0 = sqrtf(fmaxf(s0, 0.f));
    const float d1 = sqrtf(fmaxf(s1, 0.f));
    const float d2 = sqrtf(fmaxf(s2, 0.f));
    const float r0 = 1.0f / (d0 + 1e-8f);
    const float r1 = 1.0f / (d1 + 1e-8f);
    const float r2 = 1.0f / (d2 + 1e-8f);
    const float rs = 1.0f / (r0 + r1 + r2);
    g_wk[q * 3 + 0] = r0 * rs;  g_ik[q * 3 + 0] = i0;
    g_wk[q * 3 + 1] = r1 * rs;  g_ik[q * 3 + 1] = i1;
    g_wk[q * 3 + 2] = r2 * rs;  g_ik[q * 3 + 2] = i2;
}

// ---------------------------------------------------------------------------
// GEMM 2: h = LN(feats; ln2) @ w2 + b2   [NTOT x 384] -> [NTOT x 192]
// 192 threads, 32 rows/block, packed f32x2 accumulation (16 row-pairs/thread)
// dynamic smem: xs[384][36] floats (row-pair transposed, 144B row pitch)
// ---------------------------------------------------------------------------
__global__ __launch_bounds__(192) void k_ln_gemm2(
    const float* __restrict__ feats,
    const float* __restrict__ ln_g, const float* __restrict__ ln_b,
    const float* __restrict__ w,    const float* __restrict__ bias)
{
    extern __shared__ float xs[];          // [CIN][36]
    const int tid = threadIdx.x, wid = tid >> 5, lane = tid & 31;
    const int row0 = blockIdx.x * 32;

    for (int r = wid; r < 32; r += 6) {
        const float* x = feats + (size_t)(row0 + r) * CIN;
        float v[12];
        float s = 0.f, ss = 0.f;
#pragma unroll
        for (int t = 0; t < 12; t++) {
            v[t] = x[lane + 32 * t];
            s  += v[t];
            ss += v[t] * v[t];
        }
        s  = warp_sum(s);
        ss = warp_sum(ss);
        const float mu  = s * (1.0f / CIN);
        const float inv = rsqrtf(ss * (1.0f / CIN) - mu * mu + LN_EPS);
#pragma unroll
        for (int t = 0; t < 12; t++) {
            const int k = lane + 32 * t;
            xs[k * 36 + r] = (v[t] - mu) * inv * ln_g[k] + ln_b[k];
        }
    }
    __syncthreads();

    const int j = tid;
    ull acc[16];
#pragma unroll
    for (int p = 0; p < 16; p++) acc[p] = 0ull;

#pragma unroll 2
    for (int k = 0; k < CIN; k++) {
        const float wk = w[(size_t)k * COUT + j];
        const ull ww = pack2(wk, wk);
        const double2* xr = (const double2*)(xs + k * 36);
#pragma unroll
        for (int c = 0; c < 8; c++) {
            const double2 d = xr[c];
            acc[2 * c]     = ffma2(__double_as_longlong(d.x), ww, acc[2 * c]);
            acc[2 * c + 1] = ffma2(__double_as_longlong(d.y), ww, acc[2 * c + 1]);
        }
    }
    const float bb = bias[j];
#pragma unroll
    for (int p = 0; p < 16; p++) {
        float lo, hi; unpack2(acc[p], lo, hi);
        g_h[(size_t)(row0 + 2 * p)     * COUT + j] = lo + bb;
        g_h[(size_t)(row0 + 2 * p + 1) * COUT + j] = hi + bb;
    }
}

// ---------------------------------------------------------------------------
// GEMM 1: out = LN(support_feats; ln1) @ w1 + b1 + interp-gather(g_h)
// ---------------------------------------------------------------------------
__global__ __launch_bounds__(192) void k_ln_gemm1(
    const float* __restrict__ sfeats,
    const float* __restrict__ ln_g, const float* __restrict__ ln_b,
    const float* __restrict__ w,    const float* __restrict__ bias,
    float* __restrict__ out)
{
    __shared__ __align__(16) float xs[COUT * 36];   // 27.6 KB
    __shared__ float sw[32][3];
    __shared__ int   si[32][3];
    const int tid = threadIdx.x, wid = tid >> 5, lane = tid & 31;
    const int row0 = blockIdx.x * 32;

    if (tid < 32) {
        const int row = row0 + tid;
#pragma unroll
        for (int c = 0; c < 3; c++) {
            sw[tid][c] = g_wk[row * 3 + c];
            si[tid][c] = g_ik[row * 3 + c];
        }
    }

    for (int r = wid; r < 32; r += 6) {
        const float* x = sfeats + (size_t)(row0 + r) * COUT;
        float v[6];
        float s = 0.f, ss = 0.f;
#pragma unroll
        for (int t = 0; t < 6; t++) {
            v[t] = x[lane + 32 * t];
            s  += v[t];
            ss += v[t] * v[t];
        }
        s  = warp_sum(s);
        ss = warp_sum(ss);
        const float mu  = s * (1.0f / COUT);
        const float inv = rsqrtf(ss * (1.0f / COUT) - mu * mu + LN_EPS);
#pragma unroll
        for (int t = 0; t < 6; t++) {
            const int k = lane + 32 * t;
            xs[k * 36 + r] = (v[t] - mu) * inv * ln_g[k] + ln_b[k];
        }
    }
    __syncthreads();

    const int j = tid;
    ull acc[16];
#pragma unroll
    for (int p = 0; p < 16; p++) acc[p] = 0ull;

#pragma unroll 2
    for (int k = 0; k < COUT; k++) {
        const float wk = w[(size_t)k * COUT + j];
        const ull ww = pack2(wk, wk);
        const double2* xr = (const double2*)(xs + k * 36);
#pragma unroll
        for (int c = 0; c < 8; c++) {
            const double2 d = xr[c];
            acc[2 * c]     = ffma2(__double_as_longlong(d.x), ww, acc[2 * c]);
            acc[2 * c + 1] = ffma2(__double_as_longlong(d.y), ww, acc[2 * c + 1]);
        }
    }

    const float bb = bias[j];
#pragma unroll
    for (int p = 0; p < 16; p++) {
        float lo, hi; unpack2(acc[p], lo, hi);
#pragma unroll
        for (int hlf = 0; hlf < 2; hlf++) {
            const int r = 2 * p + hlf;
            float v = (hlf ? hi : lo) + bb;
            v = fmaf(sw[r][0], g_h[(size_t)si[r][0] * COUT + j], v);
            v = fmaf(sw[r][1], g_h[(size_t)si[r][1] * COUT + j], v);
            v = fmaf(sw[r][2], g_h[(size_t)si[r][2] * COUT + j], v);
            out[(size_t)(row0 + r) * COUT + j] = v;
        }
    }
}

// ---------------------------------------------------------------------------
// tail: support_xyz pass-through + offsets
// ---------------------------------------------------------------------------
__global__ void k_tail_fast(const float* __restrict__ sxyz,
                            const int* __restrict__ soff,
                            float* __restrict__ out)
{
    const int i = blockIdx.x * blockDim.x + threadIdx.x;
    const int n4 = MTOT * 3 / 4;           // 49152 float4s
    const size_t base = (size_t)MTOT * COUT;
    if (i < n4) {
        ((float4*)(out + base))[i] = ((const float4*)sxyz)[i];
    } else if (i - n4 < NB) {
        out[base + (size_t)MTOT * 3 + (i - n4)] = (float)soff[i - n4];
    }
}

__global__ void k_tail_scalar(const float* __restrict__ sxyz,
                              const int* __restrict__ soff,
                              float* __restrict__ out, int extra)
{
    const int i = blockIdx.x * blockDim.x + threadIdx.x;
    if (i >= extra) return;
    const size_t base = (size_t)MTOT * COUT;
    if (i < MTOT * 3) out[base + i] = sxyz[i];
    else if (i - MTOT * 3 < NB) out[base + i] = (float)soff[i - MTOT * 3];
}

// ---------------------------------------------------------------------------
extern "C" void kernel_launch(void* const* d_in, const int* in_sizes, int n_in,
                              void* d_out, int out_size)
{
    const float* feats  = (const float*)d_in[0];
    const float* xyz    = (const float*)d_in[1];
    const float* sxyz   = (const float*)d_in[2];
    const float* sfeats = (const float*)d_in[3];
    const int*   soff   = (const int*)  d_in[5];
    const float* ln1_g  = (const float*)d_in[6];
    const float* ln1_b  = (const float*)d_in[7];
    const float* w1     = (const float*)d_in[8];
    const float* b1     = (const float*)d_in[9];
    const float* ln2_g  = (const float*)d_in[10];
    const float* ln2_b  = (const float*)d_in[11];
    const float* w2     = (const float*)d_in[12];
    const float* b2     = (const float*)d_in[13];
    float* out = (float*)d_out;

    const int smem2 = CIN * 36 * (int)sizeof(float);   // 55296 B
    cudaFuncSetAttribute(k_ln_gemm2, cudaFuncAttributeMaxDynamicSharedMemorySize, smem2);

    // grid build (tiny)
    k_grid_zero<<<2, 1024>>>();
    k_grid_count<<<NTOT / 256, 256>>>(xyz);
    k_grid_scan<<<1, 1024>>>();
    k_grid_scatter<<<NTOT / 256, 256>>>(xyz);

    // branch 2: LN + Linear on coarse feats (f32x2 packed)
    k_ln_gemm2<<<NTOT / 32, 192, smem2>>>(feats, ln2_g, ln2_b, w2, b2);

    // exact 3-NN via cell grid + ring expansion
    k_knn_grid<<<MTOT / 256, 256>>>(sxyz);

    // branch 1: LN + Linear + fused interp gather + add
    k_ln_gemm1<<<MTOT / 32, 192>>>(sfeats, ln1_g, ln1_b, w1, b1, out);

    const long long main_sz = (long long)MTOT * COUT;
    if ((long long)out_size > main_sz) {
        const long long extra = (long long)out_size - main_sz;
        if (extra >= (long long)MTOT * 3 + NB) {
            const int n = MTOT * 3 / 4 + NB;
            k_tail_fast<<<(n + 255) / 256, 256>>>(sxyz, soff, out);
        } else {
            k_tail_scalar<<<((int)extra + 255) / 256, 256>>>(sxyz, soff, out, (int)extra);
        }
    }
}